// round 7
// baseline (speedup 1.0000x reference)
#include <cuda_runtime.h>
#include <cstdint>

// DeepProbLogAdditionReasoner: per-row conv of two length-10 pdfs -> 19 bins, normalized.
// Round-7: pipelined persistent kernel + high occupancy.
//   - double-buffered cp.async input staging (prefetch t+1 during compute of t)
//   - output restaged INTO the consumed input buffer (no separate sout)
//     -> smem 20.5KB/CTA -> 11 CTAs/SM (was 7)
//   - single bulk async store per tile, drained at next iteration top
//   - __launch_bounds__(128,11) to hold regs <= 46

#define TPB 128
#define NV4_IN   (TPB * 10 / 4)    // 320 float4 per input array per tile
#define BUF_F    (TPB * 20)        // floats per buffer: p1 tile | p2 tile
#define OUT_BYTES (TPB * 19 * 4)   // 9728 bytes per output tile
#define MAXGRID  (152 * 11)        // CTAs at 11/SM

__device__ __forceinline__ uint32_t smem_u32(const void* p) {
    uint32_t a;
    asm("{ .reg .u64 t; cvta.to.shared.u64 t, %1; cvt.u32.u64 %0, t; }"
        : "=r"(a) : "l"(p));
    return a;
}

__device__ __forceinline__ void cp_async16(uint32_t smem_dst, const void* gmem_src) {
    asm volatile("cp.async.cg.shared.global [%0], [%1], 16;"
                 :: "r"(smem_dst), "l"(gmem_src) : "memory");
}

__global__ __launch_bounds__(TPB, 11) void dpl_add_kernel(
    const float* __restrict__ p1,
    const float* __restrict__ p2,
    float* __restrict__ out,
    int B, int nTiles)
{
    __shared__ float sbuf[2][BUF_F];

    const int tid = threadIdx.x;
    const int stride = gridDim.x;

    auto prefetch = [&](int t, int buf) {
        const float4* g14 = (const float4*)(p1 + (long long)t * TPB * 10);
        const float4* g24 = (const float4*)(p2 + (long long)t * TPB * 10);
        const uint32_t sb = smem_u32(&sbuf[buf][0]);
        #pragma unroll
        for (int i = tid; i < NV4_IN; i += TPB) {
            cp_async16(sb + i * 16,              g14 + i);
            cp_async16(sb + (NV4_IN + i) * 16,   g24 + i);
        }
    };

    int tile = blockIdx.x;

    // ---- prologue: prefetch first tile into buf 0 ----
    if (tile < nTiles && (long long)tile * TPB + TPB <= (long long)B)
        prefetch(tile, 0);
    asm volatile("cp.async.commit_group;" ::: "memory");

    for (int k = 0; tile < nTiles; k++, tile += stride) {
        const int cur = k & 1;
        const long long base = (long long)tile * TPB;
        const int rows = (B - base < TPB) ? (int)(B - base) : TPB;
        const bool full = (rows == TPB);

        // ---- drain bulk store that was reading sbuf[cur^1] (issued 1 iter ago)
        //      before prefetch overwrites it ----
        if (tid == 0)
            asm volatile("cp.async.bulk.wait_group 0;" ::: "memory");
        __syncthreads();

        // ---- prefetch next tile into the other buffer ----
        const int nextTile = tile + stride;
        if (nextTile < nTiles && (long long)nextTile * TPB + TPB <= (long long)B)
            prefetch(nextTile, cur ^ 1);
        asm volatile("cp.async.commit_group;" ::: "memory");

        // ---- current buffer ready (next prefetch stays in flight) ----
        asm volatile("cp.async.wait_group 1;" ::: "memory");

        if (!full) {  // last partial tile: scalar synchronous load
            const float* g1 = p1 + base * 10;
            const float* g2 = p2 + base * 10;
            const int n = rows * 10;
            for (int i = tid; i < n; i += TPB) {
                sbuf[cur][i]            = g1[i];
                sbuf[cur][TPB * 10 + i] = g2[i];
            }
        }
        __syncthreads();

        // ---- compute: per-row convolution + normalize (regs: b[10] + r[19]) ----
        float r[19];
        {
            float b[10];
            #pragma unroll
            for (int j = 0; j < 10; j++)
                b[j] = sbuf[cur][TPB * 10 + tid * 10 + j];
            #pragma unroll
            for (int q = 0; q < 19; q++) r[q] = 0.0f;
            #pragma unroll
            for (int i = 0; i < 10; i++) {
                const float ai = sbuf[cur][tid * 10 + i];
                #pragma unroll
                for (int j = 0; j < 10; j++)
                    r[i + j] = fmaf(ai, b[j], r[i + j]);
            }
            float s = 0.0f;
            #pragma unroll
            for (int q = 0; q < 19; q++) s += r[q];
            const float inv = 1.0f / (s + 1e-9f);
            #pragma unroll
            for (int q = 0; q < 19; q++) r[q] *= inv;
        }
        __syncthreads();   // all input reads of sbuf[cur] done before overwrite

        // ---- restage output into the just-consumed buffer (stride 19) ----
        if (tid < rows) {
            #pragma unroll
            for (int q = 0; q < 19; q++) sbuf[cur][tid * 19 + q] = r[q];
        }
        __syncthreads();

        if (full) {
            if (tid == 0) {
                asm volatile("fence.proxy.async.shared::cta;" ::: "memory");
                float* go = out + base * 19;
                asm volatile(
                    "cp.async.bulk.global.shared::cta.bulk_group [%0], [%1], %2;"
                    :: "l"(go), "r"(smem_u32(&sbuf[cur][0])),
                       "r"((uint32_t)OUT_BYTES)
                    : "memory");
                asm volatile("cp.async.bulk.commit_group;" ::: "memory");
            }
            // drain overlapped by next iteration (waited at loop top)
        } else {
            float* go = out + base * 19;
            const int n = rows * 19;
            for (int i = tid; i < n; i += TPB) go[i] = sbuf[cur][i];
        }
    }

    // ---- epilogue: last bulk store must complete before CTA retires ----
    if (tid == 0)
        asm volatile("cp.async.bulk.wait_group 0;" ::: "memory");
}

extern "C" void kernel_launch(void* const* d_in, const int* in_sizes, int n_in,
                              void* d_out, int out_size) {
    const float* p1 = (const float*)d_in[0];
    const float* p2 = (const float*)d_in[1];
    float* out = (float*)d_out;
    const int B = in_sizes[0] / 10;
    const int nTiles = (B + TPB - 1) / TPB;
    // balanced persistent grid: uniform tiles/CTA, capped at single-wave capacity
    int grid = nTiles;
    if (grid > MAXGRID) {
        const int tilesPerCta = (nTiles + MAXGRID - 1) / MAXGRID;
        grid = (nTiles + tilesPerCta - 1) / tilesPerCta;
    }
    dpl_add_kernel<<<grid, TPB>>>(p1, p2, out, B, nTiles);
}